// round 15
// baseline (speedup 1.0000x reference)
#include <cuda_runtime.h>
#include <cstdint>

// Problem dims
#define BB 8
#define DD 1024
#define TT 8192
#define NCB 9
#define KK 1024
#define NT (BB*TT)        // 65536 tokens
#define CN (NCB*8)        // 72
#define NP (NT/2)         // 32768 token pairs

// Output layout (float32, tuple flattened in order)
#define OFF_CODES ((size_t)BB*DD*TT)                  // 67108864
#define OFF_LAT   (OFF_CODES + (size_t)BB*NCB*TT)     // 67698688
#define OFF_CL    (OFF_LAT + (size_t)BB*CN*TT)        // 72417280

#define THREADS 128
#define NBLK 256          // 256*128 = 32768 = NP exactly

// Dynamic smem OVERLAY: streaming tables vs argmin tables, phase-disjoint.
#define SM_WIN 0          // 8192 f
#define SM_WO0 8192       // 8192 f : wout m0
#define SM_WO1 16384      // 8192 f : wout m0+1 (2-proj stages)
#define SM_OB0 24576      // 1024 f
#define SM_OB1 25600      // 1024 f
#define SM_CB2 0          // 8192 f (overlay)
#define SM_CC2 8192       // 1024 f (overlay)
#define SMEM_TOT (26624*4)   // 106496 bytes -> 2 blocks/SM

// Scratch (__device__ globals: allowed; no runtime allocation)
__device__ float g_resA[(size_t)BB*DD*TT];           // res1, res5
__device__ float g_resB[(size_t)BB*DD*TT];           // res3, res7
__device__ __align__(16) float g_WinT[NCB*DD*8];     // [n][d][c]
__device__ __align__(16) float g_WoutT[NCB*DD*8];    // [n][d][c]
__device__ __align__(16) float g_cbn[NCB*KK*8];      // normalized codebook (ref fp32 semantics)
__device__ __align__(16) float g_cc[NCB*KK];         // sum(c_n*c_n)
__device__ __align__(16) float g_lpart[NBLK];

// ---------------------------------------------------------------------------
// f32x2 packed helpers (each lane an exact IEEE fp32 op)
// ---------------------------------------------------------------------------
__device__ __forceinline__ unsigned long long pk2(float lo, float hi) {
    unsigned long long r;
    asm("mov.b64 %0, {%1, %2};" : "=l"(r) : "f"(lo), "f"(hi));
    return r;
}
__device__ __forceinline__ void upk2(unsigned long long v, float& lo, float& hi) {
    asm("mov.b64 {%0, %1}, %2;" : "=f"(lo), "=f"(hi) : "l"(v));
}
__device__ __forceinline__ unsigned long long ffma2(unsigned long long a, unsigned long long b, unsigned long long c) {
    unsigned long long r;
    asm("fma.rn.f32x2 %0, %1, %2, %3;" : "=l"(r) : "l"(a), "l"(b), "l"(c));
    return r;
}
__device__ __forceinline__ unsigned long long fmul2(unsigned long long a, unsigned long long b) {
    unsigned long long r;
    asm("mul.rn.f32x2 %0, %1, %2;" : "=l"(r) : "l"(a), "l"(b));
    return r;
}
__device__ __forceinline__ unsigned long long fadd2(unsigned long long a, unsigned long long b) {
    unsigned long long r;
    asm("add.rn.f32x2 %0, %1, %2;" : "=l"(r) : "l"(a), "l"(b));
    return r;
}
#define SGN2 0x8000000080000000ull

// ---------------------------------------------------------------------------
// Prep: weight-norm input rows (fp64 norms), store [n][d][8c]
// ---------------------------------------------------------------------------
__global__ void kp_win(const float* __restrict__ in_v, const float* __restrict__ in_g) {
    const int row = blockIdx.x;               // 0..71 = n*8 + c
    const int n = row >> 3, c = row & 7;
    const float* src = in_v + (size_t)row * DD;
    __shared__ double red[256];
    double ss = 0.0;
    for (int d = threadIdx.x; d < DD; d += 256) { double v = src[d]; ss += v*v; }
    red[threadIdx.x] = ss; __syncthreads();
    for (int s = 128; s > 0; s >>= 1) {
        if (threadIdx.x < s) red[threadIdx.x] += red[threadIdx.x + s];
        __syncthreads();
    }
    const float scale = (float)((double)in_g[row] / sqrt(red[0]));
    for (int d = threadIdx.x; d < DD; d += 256)
        g_WinT[(size_t)n*DD*8 + d*8 + c] = src[d] * scale;
}

// ---------------------------------------------------------------------------
// Prep: weight-norm output rows (norm over C=8, fp64), store [n][d][8c]
// ---------------------------------------------------------------------------
__global__ void kp_wout(const float* __restrict__ out_v, const float* __restrict__ out_g) {
    const int i = blockIdx.x * 256 + threadIdx.x;   // (n, d)
    if (i >= NCB*DD) return;
    const int n = i / DD, d = i - n*DD;
    const float* v = out_v + (size_t)i * 8;
    double ss = 0.0;
    #pragma unroll
    for (int c = 0; c < 8; c++) { double x = v[c]; ss += x*x; }
    const float sc = (float)((double)out_g[i] / sqrt(ss));
    #pragma unroll
    for (int c = 0; c < 8; c++) g_WoutT[(size_t)n*DD*8 + d*8 + c] = v[c] * sc;
}

// ---------------------------------------------------------------------------
// Prep: normalized codebook + cc = sum(c_n^2), replicating fp32 elementwise ops
// ---------------------------------------------------------------------------
__global__ void kp_cb(const float* __restrict__ cb) {
    const int r = blockIdx.x * 256 + threadIdx.x;   // (n, k)
    if (r >= NCB*KK) return;
    const float* v = cb + (size_t)r * 8;
    float ss = 0.f;
    #pragma unroll
    for (int c = 0; c < 8; c++) ss = __fadd_rn(ss, __fmul_rn(v[c], v[c]));
    const float nr = fmaxf(__fsqrt_rn(ss), 1e-12f);
    float cn[8];
    #pragma unroll
    for (int c = 0; c < 8; c++) cn[c] = __fdiv_rn(v[c], nr);
    #pragma unroll
    for (int c = 0; c < 8; c++) g_cbn[(size_t)r*8 + c] = cn[c];
    float s2 = 0.f;
    #pragma unroll
    for (int c = 0; c < 8; c++) s2 = __fadd_rn(s2, __fmul_rn(cn[c], cn[c]));
    g_cc[r] = s2;
}

// ---------------------------------------------------------------------------
// Mega kernel: one thread owns TWO adjacent tokens through 9 stages + final.
// Every-OTHER residual checkpointing; two-projection fly-recompute stages.
// Arithmetic byte-identical to the R14 passing kernel. R15 delta (load
// scheduling only): ROLLING depth-32 prefetch — consume slot i, immediately
// reload it with element d+32; 32 u64 storage gives ~32 loads in flight.
// ---------------------------------------------------------------------------
__global__ void __launch_bounds__(THREADS, 2) k_mega(const float* __restrict__ z,
                                                     const float* __restrict__ in_b,
                                                     const float* __restrict__ out_b,
                                                     const float* __restrict__ cb_raw,
                                                     float* __restrict__ out) {
    extern __shared__ float smf[];
    __shared__ float red[THREADS];

    const int tid = threadIdx.x;
    const int p = blockIdx.x * THREADS + tid;    // 0..32767, exact
    const int token = 2 * p;
    const int b = token >> 13;
    const int t = token & (TT - 1);
    const size_t off = (size_t)b*DD*TT + t;

    float zqA0[8] = {0,0,0,0,0,0,0,0}, zqA1[8] = {0,0,0,0,0,0,0,0};   // stage n-1
    float zqB0[8] = {0,0,0,0,0,0,0,0}, zqB1[8] = {0,0,0,0,0,0,0,0};   // stage n-2
    float lacc = 0.f;

    for (int n = 0; n < NCB; n++) {
        const int nproj = (n == 0) ? 0 : (((n & 1) && n >= 3) ? 2 : 1);
        const int m0 = n - nproj;
        const float* rin = (n <= 1) ? z
                          : ((n == 2 || n == 3 || n == 6 || n == 7) ? (const float*)g_resA
                                                                    : (const float*)g_resB);
        float* wr = nullptr;
        if (n == 1) wr = g_resA;
        else if (n == 3) wr = g_resB;
        else if (n == 5) wr = g_resA;
        else if (n == 7) wr = g_resB;

        // ---- load STREAMING tables into overlay ----
        __syncthreads();   // prev stage argmin done with smem
        for (int i = tid; i < DD*8; i += THREADS) smf[SM_WIN + i] = g_WinT[(size_t)n*DD*8 + i];
        if (nproj >= 1) {
            for (int i = tid; i < DD*8; i += THREADS)
                smf[SM_WO0 + i] = g_WoutT[(size_t)m0*DD*8 + i];
            for (int i = tid; i < DD; i += THREADS)
                smf[SM_OB0 + i] = out_b[m0*DD + i];
        }
        if (nproj == 2) {
            for (int i = tid; i < DD*8; i += THREADS)
                smf[SM_WO1 + i] = g_WoutT[(size_t)(m0 + 1)*DD*8 + i];
            for (int i = tid; i < DD; i += THREADS)
                smf[SM_OB1 + i] = out_b[(m0 + 1)*DD + i];
        }
        __syncthreads();

        unsigned long long zp2[8], za2[8];
        #pragma unroll
        for (int c = 0; c < 8; c++) {
            zp2[c] = (nproj == 2) ? pk2(zqB0[c], zqB1[c]) : pk2(zqA0[c], zqA1[c]);
            za2[c] = pk2(zqA0[c], zqA1[c]);
        }

        // ---- Phase 1: rolling depth-32 stream, proj(s), z_e ----
        unsigned long long acc[8] = {0,0,0,0,0,0,0,0};
        unsigned long long rbuf[32];
        #pragma unroll
        for (int i = 0; i < 32; i++)
            rbuf[i] = *(const unsigned long long*)(rin + off + (size_t)i*TT);

        for (int d0 = 0; d0 < DD; d0 += 32) {
            const bool more = (d0 + 32) < DD;
            #pragma unroll
            for (int i = 0; i < 32; i++) {
                const int d = d0 + i;
                unsigned long long r2 = rbuf[i];
                // rolling reload: slot i gets element d+32 (issued early, no dep)
                if (more)
                    rbuf[i] = *(const unsigned long long*)(rin + off + (size_t)(d + 32)*TT);
                if (nproj >= 1) {
                    const float4 wa = *(const float4*)&smf[SM_WO0 + d*8];
                    const float4 wb = *(const float4*)&smf[SM_WO0 + d*8 + 4];
                    unsigned long long dt = ffma2(pk2(wa.x, wa.x), zp2[0], 0ull);
                    dt = ffma2(pk2(wa.y, wa.y), zp2[1], dt);
                    dt = ffma2(pk2(wa.z, wa.z), zp2[2], dt);
                    dt = ffma2(pk2(wa.w, wa.w), zp2[3], dt);
                    dt = ffma2(pk2(wb.x, wb.x), zp2[4], dt);
                    dt = ffma2(pk2(wb.y, wb.y), zp2[5], dt);
                    dt = ffma2(pk2(wb.z, wb.z), zp2[6], dt);
                    dt = ffma2(pk2(wb.w, wb.w), zp2[7], dt);
                    const float obv = smf[SM_OB0 + d];
                    const unsigned long long pr = fadd2(dt, pk2(obv, obv));  // dot + ob
                    r2 = fadd2(r2, pr ^ SGN2);                                // rn(r - pr)
                }
                if (nproj == 2) {
                    const float4 wa = *(const float4*)&smf[SM_WO1 + d*8];
                    const float4 wb = *(const float4*)&smf[SM_WO1 + d*8 + 4];
                    unsigned long long dt = ffma2(pk2(wa.x, wa.x), za2[0], 0ull);
                    dt = ffma2(pk2(wa.y, wa.y), za2[1], dt);
                    dt = ffma2(pk2(wa.z, wa.z), za2[2], dt);
                    dt = ffma2(pk2(wa.w, wa.w), za2[3], dt);
                    dt = ffma2(pk2(wb.x, wb.x), za2[4], dt);
                    dt = ffma2(pk2(wb.y, wb.y), za2[5], dt);
                    dt = ffma2(pk2(wb.z, wb.z), za2[6], dt);
                    dt = ffma2(pk2(wb.w, wb.w), za2[7], dt);
                    const float obv = smf[SM_OB1 + d];
                    const unsigned long long pr = fadd2(dt, pk2(obv, obv));
                    r2 = fadd2(r2, pr ^ SGN2);
                }
                if (wr) *(unsigned long long*)(wr + off + (size_t)d*TT) = r2;
                const float4 na = *(const float4*)&smf[SM_WIN + d*8];
                const float4 nb = *(const float4*)&smf[SM_WIN + d*8 + 4];
                acc[0] = ffma2(pk2(na.x, na.x), r2, acc[0]);
                acc[1] = ffma2(pk2(na.y, na.y), r2, acc[1]);
                acc[2] = ffma2(pk2(na.z, na.z), r2, acc[2]);
                acc[3] = ffma2(pk2(na.w, na.w), r2, acc[3]);
                acc[4] = ffma2(pk2(nb.x, nb.x), r2, acc[4]);
                acc[5] = ffma2(pk2(nb.y, nb.y), r2, acc[5]);
                acc[6] = ffma2(pk2(nb.z, nb.z), r2, acc[6]);
                acc[7] = ffma2(pk2(nb.w, nb.w), r2, acc[7]);
            }
        }

        // ---- swap overlay: load ARGMIN tables ----
        __syncthreads();   // streaming done with win/wo/ob
        for (int i = tid; i < KK*8; i += THREADS) {
            const int k = i >> 3, c = i & 7;
            smf[SM_CB2 + (k >> 1)*16 + c*2 + (k & 1)] = g_cbn[(size_t)n*KK*8 + i];
        }
        for (int k = tid; k < KK; k += THREADS) smf[SM_CC2 + k] = g_cc[n*KK + k];
        __syncthreads();

        // ---- Phase 2: z_e per token, normalize (identical scalar ops) ----
        float e0[8], e1[8];
        #pragma unroll
        for (int c = 0; c < 8; c++) {
            upk2(acc[c], e0[c], e1[c]);
            const float vb = __ldg(in_b + n*8 + c);
            e0[c] = __fadd_rn(e0[c], vb);
            e1[c] = __fadd_rn(e1[c], vb);
        }

        unsigned long long enA[8], enB[8], eepA, eepB;
        {
            float ssq = 0.f;
            #pragma unroll
            for (int c = 0; c < 8; c++) ssq = __fadd_rn(ssq, __fmul_rn(e0[c], e0[c]));
            const float rho = fmaxf(__fsqrt_rn(ssq), 1e-12f);
            float en[8], ee = 0.f;
            #pragma unroll
            for (int c = 0; c < 8; c++) en[c] = __fdiv_rn(e0[c], rho);
            #pragma unroll
            for (int c = 0; c < 8; c++) ee = __fadd_rn(ee, __fmul_rn(en[c], en[c]));
            #pragma unroll
            for (int c = 0; c < 8; c++) enA[c] = pk2(en[c], en[c]);
            eepA = pk2(ee, ee);
        }
        {
            float ssq = 0.f;
            #pragma unroll
            for (int c = 0; c < 8; c++) ssq = __fadd_rn(ssq, __fmul_rn(e1[c], e1[c]));
            const float rho = fmaxf(__fsqrt_rn(ssq), 1e-12f);
            float en[8], ee = 0.f;
            #pragma unroll
            for (int c = 0; c < 8; c++) en[c] = __fdiv_rn(e1[c], rho);
            #pragma unroll
            for (int c = 0; c < 8; c++) ee = __fadd_rn(ee, __fmul_rn(en[c], en[c]));
            #pragma unroll
            for (int c = 0; c < 8; c++) enB[c] = pk2(en[c], en[c]);
            eepB = pk2(ee, ee);
        }
        const unsigned long long m2 = pk2(-2.f, -2.f);

        // ---- argmin: per-token 4-chain first-wins, identical to R13/R14 ----
        float aA = 3.4e38f, aB = 3.4e38f, aC = 3.4e38f, aD = 3.4e38f;
        int   jA = 0, jB = 0, jC = 0, jD = 0;
        float bA_ = 3.4e38f, bB_ = 3.4e38f, bC_ = 3.4e38f, bD_ = 3.4e38f;
        int   kA = 0, kB = 0, kC = 0, kD = 0;
        const unsigned long long* cbu = (const unsigned long long*)&smf[SM_CB2];
        const unsigned long long* ccu = (const unsigned long long*)&smf[SM_CC2];
        for (int k2 = 0; k2 < KK/2; k2 += 2) {
            const ulonglong2 ca0 = *(const ulonglong2*)(cbu + k2*8);
            const ulonglong2 cb0 = *(const ulonglong2*)(cbu + k2*8 + 2);
            const ulonglong2 cc0 = *(const ulonglong2*)(cbu + k2*8 + 4);
            const ulonglong2 cd0 = *(const ulonglong2*)(cbu + k2*8 + 6);
            const ulonglong2 ca1 = *(const ulonglong2*)(cbu + (k2+1)*8);
            const ulonglong2 cb1 = *(const ulonglong2*)(cbu + (k2+1)*8 + 2);
            const ulonglong2 cc1 = *(const ulonglong2*)(cbu + (k2+1)*8 + 4);
            const ulonglong2 cd1 = *(const ulonglong2*)(cbu + (k2+1)*8 + 6);
            const unsigned long long ccv0 = ccu[k2], ccv1 = ccu[k2+1];
            {
                unsigned long long dp0 = fmul2(enA[0], ca0.x);
                unsigned long long dp1 = fmul2(enA[0], ca1.x);
                dp0 = ffma2(enA[1], ca0.y, dp0);  dp1 = ffma2(enA[1], ca1.y, dp1);
                dp0 = ffma2(enA[2], cb0.x, dp0);  dp1 = ffma2(enA[2], cb1.x, dp1);
                dp0 = ffma2(enA[3], cb0.y, dp0);  dp1 = ffma2(enA[3], cb1.y, dp1);
                dp0 = ffma2(enA[4], cc0.x, dp0);  dp1 = ffma2(enA[4], cc1.x, dp1);
                dp0 = ffma2(enA[5], cc0.y, dp0);  dp1 = ffma2(enA[5], cc1.y, dp1);
                dp0 = ffma2(enA[6], cd0.x, dp0);  dp1 = ffma2(enA[6], cd1.x, dp1);
                dp0 = ffma2(enA[7], cd0.y, dp0);  dp1 = ffma2(enA[7], cd1.y, dp1);
                const unsigned long long t0 = ffma2(m2, dp0, eepA);
                const unsigned long long t1 = ffma2(m2, dp1, eepA);
                const unsigned long long di0 = fadd2(t0, ccv0);
                const unsigned long long di1 = fadd2(t1, ccv1);
                float d0v, d1v, d2v, d3v;
                upk2(di0, d0v, d1v); upk2(di1, d2v, d3v);
                if (d0v < aA) { aA = d0v; jA = 2*k2; }
                if (d1v < aB) { aB = d1v; jB = 2*k2 + 1; }
                if (d2v < aC) { aC = d2v; jC = 2*k2 + 2; }
                if (d3v < aD) { aD = d3v; jD = 2*k2 + 3; }
            }
            {
                unsigned long long dp0 = fmul2(enB[0], ca0.x);
                unsigned long long dp1 = fmul2(enB[0], ca1.x);
                dp0 = ffma2(enB[1], ca0.y, dp0);  dp1 = ffma2(enB[1], ca1.y, dp1);
                dp0 = ffma2(enB[2], cb0.x, dp0);  dp1 = ffma2(enB[2], cb1.x, dp1);
                dp0 = ffma2(enB[3], cb0.y, dp0);  dp1 = ffma2(enB[3], cb1.y, dp1);
                dp0 = ffma2(enB[4], cc0.x, dp0);  dp1 = ffma2(enB[4], cc1.x, dp1);
                dp0 = ffma2(enB[5], cc0.y, dp0);  dp1 = ffma2(enB[5], cc1.y, dp1);
                dp0 = ffma2(enB[6], cd0.x, dp0);  dp1 = ffma2(enB[6], cd1.x, dp1);
                dp0 = ffma2(enB[7], cd0.y, dp0);  dp1 = ffma2(enB[7], cd1.y, dp1);
                const unsigned long long t0 = ffma2(m2, dp0, eepB);
                const unsigned long long t1 = ffma2(m2, dp1, eepB);
                const unsigned long long di0 = fadd2(t0, ccv0);
                const unsigned long long di1 = fadd2(t1, ccv1);
                float d0v, d1v, d2v, d3v;
                upk2(di0, d0v, d1v); upk2(di1, d2v, d3v);
                if (d0v < bA_) { bA_ = d0v; kA = 2*k2; }
                if (d1v < bB_) { bB_ = d1v; kB = 2*k2 + 1; }
                if (d2v < bC_) { bC_ = d2v; kC = 2*k2 + 2; }
                if (d3v < bD_) { bD_ = d3v; kD = 2*k2 + 3; }
            }
        }
        float best0 = aA; int bi0 = jA;
        if (aB < best0 || (aB == best0 && jB < bi0)) { best0 = aB; bi0 = jB; }
        if (aC < best0 || (aC == best0 && jC < bi0)) { best0 = aC; bi0 = jC; }
        if (aD < best0 || (aD == best0 && jD < bi0)) { best0 = aD; bi0 = jD; }
        float best1 = bA_; int bi1 = kA;
        if (bB_ < best1 || (bB_ == best1 && kB < bi1)) { best1 = bB_; bi1 = kB; }
        if (bC_ < best1 || (bC_ == best1 && kC < bi1)) { best1 = bC_; bi1 = kC; }
        if (bD_ < best1 || (bD_ == best1 && kD < bi1)) { best1 = bD_; bi1 = kD; }

        // ---- Phase 3: winners, straight-through, outputs ----
        const float* q0p = cb_raw + ((size_t)n*KK + bi0)*8;
        const float* q1p = cb_raw + ((size_t)n*KK + bi1)*8;
        const float4 qa0 = __ldg((const float4*)q0p);
        const float4 qa1 = __ldg((const float4*)(q0p + 4));
        const float4 qb0 = __ldg((const float4*)q1p);
        const float4 qb1 = __ldg((const float4*)(q1p + 4));
        const float q0[8] = {qa0.x, qa0.y, qa0.z, qa0.w, qa1.x, qa1.y, qa1.z, qa1.w};
        const float q1[8] = {qb0.x, qb0.y, qb0.z, qb0.w, qb1.x, qb1.y, qb1.z, qb1.w};

        #pragma unroll
        for (int c = 0; c < 8; c++) {
            const float dl0 = __fsub_rn(e0[c], q0[c]);
            lacc = fmaf(dl0, dl0, lacc);
            const float dl1 = __fsub_rn(e1[c], q1[c]);
            lacc = fmaf(dl1, dl1, lacc);
            zqB0[c] = zqA0[c]; zqB1[c] = zqA1[c];
            zqA0[c] = __fadd_rn(e0[c], __fsub_rn(q0[c], e0[c]));
            zqA1[c] = __fadd_rn(e1[c], __fsub_rn(q1[c], e1[c]));
        }

        *(float2*)&out[OFF_CODES + (size_t)b*NCB*TT + (size_t)n*TT + t] =
            make_float2((float)bi0, (float)bi1);
        #pragma unroll
        for (int c = 0; c < 8; c++)
            *(float2*)&out[OFF_LAT + (size_t)b*CN*TT + (size_t)(n*8 + c)*TT + t] =
                make_float2(e0[c], e1[c]);
    }

    // ---- Final pass: res7(B) -> fly proj7 (zqB) -> proj8 (zqA) -> out = z - res9 ----
    __syncthreads();
    for (int i = tid; i < DD*8; i += THREADS) {
        smf[SM_WO0 + i] = g_WoutT[(size_t)7*DD*8 + i];
        smf[SM_WO1 + i] = g_WoutT[(size_t)8*DD*8 + i];
    }
    for (int i = tid; i < DD; i += THREADS) {
        smf[SM_OB0 + i] = out_b[7*DD + i];
        smf[SM_OB1 + i] = out_b[8*DD + i];
    }
    __syncthreads();

    {
        unsigned long long zb2[8], za2[8];
        #pragma unroll
        for (int c = 0; c < 8; c++) {
            zb2[c] = pk2(zqB0[c], zqB1[c]);
            za2[c] = pk2(zqA0[c], zqA1[c]);
        }
        // rolling depth-8 for both streams (16 u64 live)
        unsigned long long rb[8], zb[8];
        #pragma unroll
        for (int i = 0; i < 8; i++) {
            rb[i] = *(const unsigned long long*)((const float*)g_resB + off + (size_t)i*TT);
            zb[i] = *(const unsigned long long*)(z + off + (size_t)i*TT);
        }
        for (int d0 = 0; d0 < DD; d0 += 8) {
            const bool more = (d0 + 8) < DD;
            #pragma unroll
            for (int i = 0; i < 8; i++) {
                const int d = d0 + i;
                unsigned long long r2 = rb[i];
                const unsigned long long zv = zb[i];
                if (more) {
                    rb[i] = *(const unsigned long long*)((const float*)g_resB + off + (size_t)(d + 8)*TT);
                    zb[i] = *(const unsigned long long*)(z + off + (size_t)(d + 8)*TT);
                }
                {   // proj7 with zqB (exactly what stage 8 computed on the fly)
                    const float4 wa = *(const float4*)&smf[SM_WO0 + d*8];
                    const float4 wb = *(const float4*)&smf[SM_WO0 + d*8 + 4];
                    unsigned long long dt = ffma2(pk2(wa.x, wa.x), zb2[0], 0ull);
                    dt = ffma2(pk2(wa.y, wa.y), zb2[1], dt);
                    dt = ffma2(pk2(wa.z, wa.z), zb2[2], dt);
                    dt = ffma2(pk2(wa.w, wa.w), zb2[3], dt);
                    dt = ffma2(pk2(wb.x, wb.x), zb2[4], dt);
                    dt = ffma2(pk2(wb.y, wb.y), zb2[5], dt);
                    dt = ffma2(pk2(wb.z, wb.z), zb2[6], dt);
                    dt = ffma2(pk2(wb.w, wb.w), zb2[7], dt);
                    const float obv = smf[SM_OB0 + d];
                    const unsigned long long pr = fadd2(dt, pk2(obv, obv));
                    r2 = fadd2(r2, pr ^ SGN2);
                }
                {   // proj8 with zqA
                    const float4 wa = *(const float4*)&smf[SM_WO1 + d*8];
                    const float4 wb = *(const float4*)&smf[SM_WO1 + d*8 + 4];
                    unsigned long long dt = ffma2(pk2(wa.x, wa.x), za2[0], 0ull);
                    dt = ffma2(pk2(wa.y, wa.y), za2[1], dt);
                    dt = ffma2(pk2(wa.z, wa.z), za2[2], dt);
                    dt = ffma2(pk2(wa.w, wa.w), za2[3], dt);
                    dt = ffma2(pk2(wb.x, wb.x), za2[4], dt);
                    dt = ffma2(pk2(wb.y, wb.y), za2[5], dt);
                    dt = ffma2(pk2(wb.z, wb.z), za2[6], dt);
                    dt = ffma2(pk2(wb.w, wb.w), za2[7], dt);
                    const float obv = smf[SM_OB1 + d];
                    const unsigned long long pr = fadd2(dt, pk2(obv, obv));
                    r2 = fadd2(r2, pr ^ SGN2);
                }
                *(unsigned long long*)&out[off + (size_t)d*TT] = fadd2(zv, r2 ^ SGN2); // rn(z - r9)
            }
        }
    }

    // ---- loss partial ----
    red[tid] = lacc; __syncthreads();
    for (int s = THREADS/2; s > 0; s >>= 1) {
        if (tid < s) red[tid] += red[tid + s];
        __syncthreads();
    }
    if (tid == 0) g_lpart[blockIdx.x] = red[0];
}

// ---------------------------------------------------------------------------
// Deterministic loss reduce in fp64: cl == cbl (identical forward values)
// ---------------------------------------------------------------------------
__global__ void k_loss(float* __restrict__ out) {
    if (threadIdx.x != 0 || blockIdx.x != 0) return;
    double s = 0.0;
    for (int i = 0; i < NBLK; i++) s += (double)g_lpart[i];
    const float v = (float)(s / 524288.0);   // per-stage mean over B*C*T, summed
    out[OFF_CL]     = v;
    out[OFF_CL + 1] = v;
}

// ---------------------------------------------------------------------------
extern "C" void kernel_launch(void* const* d_in, const int* in_sizes, int n_in,
                              void* d_out, int out_size) {
    (void)in_sizes; (void)n_in; (void)out_size;
    const float* z     = (const float*)d_in[0];
    const float* in_v  = (const float*)d_in[1];
    const float* in_g  = (const float*)d_in[2];
    const float* in_b  = (const float*)d_in[3];
    const float* out_v = (const float*)d_in[4];
    const float* out_g = (const float*)d_in[5];
    const float* out_b = (const float*)d_in[6];
    const float* cb    = (const float*)d_in[7];
    float* out = (float*)d_out;

    cudaFuncSetAttribute(k_mega, cudaFuncAttributeMaxDynamicSharedMemorySize, SMEM_TOT);

    kp_win  <<<72, 256>>>(in_v, in_g);
    kp_wout <<<(NCB*DD + 255)/256, 256>>>(out_v, out_g);
    kp_cb   <<<(NCB*KK + 255)/256, 256>>>(cb);

    k_mega <<<NBLK, THREADS, SMEM_TOT>>>(z, in_b, out_b, cb, out);
    k_loss <<<1, 32>>>(out);
}

// round 16
// speedup vs baseline: 1.0981x; 1.0981x over previous
#include <cuda_runtime.h>
#include <cstdint>

// Problem dims
#define BB 8
#define DD 1024
#define TT 8192
#define NCB 9
#define KK 1024
#define NT (BB*TT)        // 65536 tokens
#define CN (NCB*8)        // 72
#define NP (NT/2)         // 32768 token pairs

// Output layout (float32, tuple flattened in order)
#define OFF_CODES ((size_t)BB*DD*TT)                  // 67108864
#define OFF_LAT   (OFF_CODES + (size_t)BB*NCB*TT)     // 67698688
#define OFF_CL    (OFF_LAT + (size_t)BB*CN*TT)        // 72417280

#define THREADS 128
#define NBLK 256          // 256*128 = 32768 = NP exactly

// Dynamic smem OVERLAY: streaming tables vs argmin tables vs final tables.
// Stage streaming: win[8192] wo[8192] ob[1024]          = 17408 f
// Argmin:          cb2[8192] cc2[1024]                   =  9216 f
// Final:           wo7[8192] wo8[8192] ob7[1024] ob8[1024]=18432 f  (max)
#define SM_WIN 0          // 8192 f
#define SM_WO  8192       // 8192 f
#define SM_OB  16384      // 1024 f
#define SM_CB2 0          // 8192 f (overlay)
#define SM_CC2 8192       // 1024 f (overlay)
#define SM_FW7 0          // 8192 f (final overlay)
#define SM_FW8 8192       // 8192 f
#define SM_FO7 16384      // 1024 f
#define SM_FO8 17408      // 1024 f
#define SMEM_TOT (18432*4)   // 73728 bytes -> 2 blocks/SM

// Scratch (__device__ globals: allowed; no runtime allocation)
__device__ float g_resA[(size_t)BB*DD*TT];           // res1, res3, res5, res7 (odd)
__device__ float g_resB[(size_t)BB*DD*TT];           // res2, res4, res6 (even; res8 skipped)
__device__ __align__(16) float g_WinT[NCB*DD*8];     // [n][d][c]
__device__ __align__(16) float g_WoutT[NCB*DD*8];    // [n][d][c]
__device__ __align__(16) float g_cbn[NCB*KK*8];      // normalized codebook (ref fp32 semantics)
__device__ __align__(16) float g_cc[NCB*KK];         // sum(c_n*c_n)
__device__ __align__(16) float g_lpart[NBLK];

// ---------------------------------------------------------------------------
// f32x2 packed helpers (each lane an exact IEEE fp32 op)
// ---------------------------------------------------------------------------
__device__ __forceinline__ unsigned long long pk2(float lo, float hi) {
    unsigned long long r;
    asm("mov.b64 %0, {%1, %2};" : "=l"(r) : "f"(lo), "f"(hi));
    return r;
}
__device__ __forceinline__ void upk2(unsigned long long v, float& lo, float& hi) {
    asm("mov.b64 {%0, %1}, %2;" : "=f"(lo), "=f"(hi) : "l"(v));
}
__device__ __forceinline__ unsigned long long ffma2(unsigned long long a, unsigned long long b, unsigned long long c) {
    unsigned long long r;
    asm("fma.rn.f32x2 %0, %1, %2, %3;" : "=l"(r) : "l"(a), "l"(b), "l"(c));
    return r;
}
__device__ __forceinline__ unsigned long long fmul2(unsigned long long a, unsigned long long b) {
    unsigned long long r;
    asm("mul.rn.f32x2 %0, %1, %2;" : "=l"(r) : "l"(a), "l"(b));
    return r;
}
__device__ __forceinline__ unsigned long long fadd2(unsigned long long a, unsigned long long b) {
    unsigned long long r;
    asm("add.rn.f32x2 %0, %1, %2;" : "=l"(r) : "l"(a), "l"(b));
    return r;
}
#define SGN2 0x8000000080000000ull

// ---------------------------------------------------------------------------
// Prep: weight-norm input rows (fp64 norms), store [n][d][8c]
// ---------------------------------------------------------------------------
__global__ void kp_win(const float* __restrict__ in_v, const float* __restrict__ in_g) {
    const int row = blockIdx.x;               // 0..71 = n*8 + c
    const int n = row >> 3, c = row & 7;
    const float* src = in_v + (size_t)row * DD;
    __shared__ double red[256];
    double ss = 0.0;
    for (int d = threadIdx.x; d < DD; d += 256) { double v = src[d]; ss += v*v; }
    red[threadIdx.x] = ss; __syncthreads();
    for (int s = 128; s > 0; s >>= 1) {
        if (threadIdx.x < s) red[threadIdx.x] += red[threadIdx.x + s];
        __syncthreads();
    }
    const float scale = (float)((double)in_g[row] / sqrt(red[0]));
    for (int d = threadIdx.x; d < DD; d += 256)
        g_WinT[(size_t)n*DD*8 + d*8 + c] = src[d] * scale;
}

// ---------------------------------------------------------------------------
// Prep: weight-norm output rows (norm over C=8, fp64), store [n][d][8c]
// ---------------------------------------------------------------------------
__global__ void kp_wout(const float* __restrict__ out_v, const float* __restrict__ out_g) {
    const int i = blockIdx.x * 256 + threadIdx.x;   // (n, d)
    if (i >= NCB*DD) return;
    const int n = i / DD, d = i - n*DD;
    const float* v = out_v + (size_t)i * 8;
    double ss = 0.0;
    #pragma unroll
    for (int c = 0; c < 8; c++) { double x = v[c]; ss += x*x; }
    const float sc = (float)((double)out_g[i] / sqrt(ss));
    #pragma unroll
    for (int c = 0; c < 8; c++) g_WoutT[(size_t)n*DD*8 + d*8 + c] = v[c] * sc;
}

// ---------------------------------------------------------------------------
// Prep: normalized codebook + cc = sum(c_n^2), replicating fp32 elementwise ops
// ---------------------------------------------------------------------------
__global__ void kp_cb(const float* __restrict__ cb) {
    const int r = blockIdx.x * 256 + threadIdx.x;   // (n, k)
    if (r >= NCB*KK) return;
    const float* v = cb + (size_t)r * 8;
    float ss = 0.f;
    #pragma unroll
    for (int c = 0; c < 8; c++) ss = __fadd_rn(ss, __fmul_rn(v[c], v[c]));
    const float nr = fmaxf(__fsqrt_rn(ss), 1e-12f);
    float cn[8];
    #pragma unroll
    for (int c = 0; c < 8; c++) cn[c] = __fdiv_rn(v[c], nr);
    #pragma unroll
    for (int c = 0; c < 8; c++) g_cbn[(size_t)r*8 + c] = cn[c];
    float s2 = 0.f;
    #pragma unroll
    for (int c = 0; c < 8; c++) s2 = __fadd_rn(s2, __fmul_rn(cn[c], cn[c]));
    g_cc[r] = s2;
}

// ---------------------------------------------------------------------------
// Mega kernel: R13 structure (every-stage checkpoint, single projection per
// stage, depth-32 double-buffered prefetch). R16 delta: stage 8 does NOT
// write res8 (saves one 268MB stream); final reads res7 and applies proj7
// (zq7, stashed in smem at stage-8 entry) then proj8 (zqA) — the exact
// bit-identical two-projection final proven in R14.
// ---------------------------------------------------------------------------
__global__ void __launch_bounds__(THREADS, 2) k_mega(const float* __restrict__ z,
                                                     const float* __restrict__ in_b,
                                                     const float* __restrict__ out_b,
                                                     const float* __restrict__ cb_raw,
                                                     float* __restrict__ out) {
    extern __shared__ float smf[];
    __shared__ float red[THREADS];
    __shared__ float zq7s[THREADS * 16];   // zq7 stash (per-thread, both lanes)

    const int tid = threadIdx.x;
    const int p = blockIdx.x * THREADS + tid;    // 0..32767, exact
    const int token = 2 * p;
    const int b = token >> 13;
    const int t = token & (TT - 1);
    const size_t off = (size_t)b*DD*TT + t;

    float zqA0[8] = {0,0,0,0,0,0,0,0}, zqA1[8] = {0,0,0,0,0,0,0,0};
    float lacc = 0.f;

    for (int n = 0; n < NCB; n++) {
        const float* rin = (n <= 1) ? z
                         : (((n & 1) == 0) ? (const float*)g_resA : (const float*)g_resB);
        float* wr = (n == 0 || n == 8) ? nullptr : ((n & 1) ? g_resA : g_resB);

        // stash zq7 for the final pass before stage 8 overwrites zqA
        if (n == 8) {
            #pragma unroll
            for (int c = 0; c < 8; c++) {
                zq7s[tid*16 + c]     = zqA0[c];
                zq7s[tid*16 + 8 + c] = zqA1[c];
            }
        }

        // ---- load STREAMING tables into overlay ----
        __syncthreads();   // prev stage argmin done with smem
        for (int i = tid; i < DD*8; i += THREADS) smf[SM_WIN + i] = g_WinT[(size_t)n*DD*8 + i];
        if (n >= 1) {
            for (int i = tid; i < DD*8; i += THREADS)
                smf[SM_WO + i] = g_WoutT[(size_t)(n-1)*DD*8 + i];
            for (int i = tid; i < DD; i += THREADS)
                smf[SM_OB + i] = out_b[(n-1)*DD + i];
        }
        __syncthreads();

        unsigned long long zq2[8];
        #pragma unroll
        for (int c = 0; c < 8; c++) zq2[c] = pk2(zqA0[c], zqA1[c]);

        // ---- Phase 1: stream residual pair (depth-32 u64 double buffer) ----
        unsigned long long acc[8] = {0,0,0,0,0,0,0,0};
        unsigned long long rbuf[32];
        #pragma unroll
        for (int i = 0; i < 32; i++)
            rbuf[i] = *(const unsigned long long*)(rin + off + (size_t)i*TT);

        for (int d0 = 0; d0 < DD; d0 += 32) {
            unsigned long long rnx[32];
            const bool more = (d0 + 32) < DD;
            if (more) {
                #pragma unroll
                for (int i = 0; i < 32; i++)
                    rnx[i] = *(const unsigned long long*)(rin + off + (size_t)(d0 + 32 + i)*TT);
            }
            #pragma unroll
            for (int i = 0; i < 32; i++) {
                const int d = d0 + i;
                unsigned long long r2 = rbuf[i];
                if (n >= 1) {
                    const float4 wa = *(const float4*)&smf[SM_WO + d*8];
                    const float4 wb = *(const float4*)&smf[SM_WO + d*8 + 4];
                    unsigned long long dt = ffma2(pk2(wa.x, wa.x), zq2[0], 0ull);
                    dt = ffma2(pk2(wa.y, wa.y), zq2[1], dt);
                    dt = ffma2(pk2(wa.z, wa.z), zq2[2], dt);
                    dt = ffma2(pk2(wa.w, wa.w), zq2[3], dt);
                    dt = ffma2(pk2(wb.x, wb.x), zq2[4], dt);
                    dt = ffma2(pk2(wb.y, wb.y), zq2[5], dt);
                    dt = ffma2(pk2(wb.z, wb.z), zq2[6], dt);
                    dt = ffma2(pk2(wb.w, wb.w), zq2[7], dt);
                    const float obv = smf[SM_OB + d];
                    const unsigned long long pr = fadd2(dt, pk2(obv, obv));  // dot + ob
                    r2 = fadd2(r2, pr ^ SGN2);                                // rn(r - pr)
                    if (wr) *(unsigned long long*)(wr + off + (size_t)d*TT) = r2;
                }
                const float4 na = *(const float4*)&smf[SM_WIN + d*8];
                const float4 nb = *(const float4*)&smf[SM_WIN + d*8 + 4];
                acc[0] = ffma2(pk2(na.x, na.x), r2, acc[0]);
                acc[1] = ffma2(pk2(na.y, na.y), r2, acc[1]);
                acc[2] = ffma2(pk2(na.z, na.z), r2, acc[2]);
                acc[3] = ffma2(pk2(na.w, na.w), r2, acc[3]);
                acc[4] = ffma2(pk2(nb.x, nb.x), r2, acc[4]);
                acc[5] = ffma2(pk2(nb.y, nb.y), r2, acc[5]);
                acc[6] = ffma2(pk2(nb.z, nb.z), r2, acc[6]);
                acc[7] = ffma2(pk2(nb.w, nb.w), r2, acc[7]);
            }
            if (more) {
                #pragma unroll
                for (int i = 0; i < 32; i++) rbuf[i] = rnx[i];
            }
        }

        // ---- swap overlay: load ARGMIN tables ----
        __syncthreads();   // streaming done with win/wo/ob
        for (int i = tid; i < KK*8; i += THREADS) {
            const int k = i >> 3, c = i & 7;
            smf[SM_CB2 + (k >> 1)*16 + c*2 + (k & 1)] = g_cbn[(size_t)n*KK*8 + i];
        }
        for (int k = tid; k < KK; k += THREADS) smf[SM_CC2 + k] = g_cc[n*KK + k];
        __syncthreads();

        // ---- Phase 2: z_e per token, normalize (identical scalar ops) ----
        float e0[8], e1[8];
        #pragma unroll
        for (int c = 0; c < 8; c++) {
            upk2(acc[c], e0[c], e1[c]);
            const float vb = __ldg(in_b + n*8 + c);
            e0[c] = __fadd_rn(e0[c], vb);
            e1[c] = __fadd_rn(e1[c], vb);
        }

        unsigned long long enA[8], enB[8], eepA, eepB;
        {
            float ssq = 0.f;
            #pragma unroll
            for (int c = 0; c < 8; c++) ssq = __fadd_rn(ssq, __fmul_rn(e0[c], e0[c]));
            const float rho = fmaxf(__fsqrt_rn(ssq), 1e-12f);
            float en[8], ee = 0.f;
            #pragma unroll
            for (int c = 0; c < 8; c++) en[c] = __fdiv_rn(e0[c], rho);
            #pragma unroll
            for (int c = 0; c < 8; c++) ee = __fadd_rn(ee, __fmul_rn(en[c], en[c]));
            #pragma unroll
            for (int c = 0; c < 8; c++) enA[c] = pk2(en[c], en[c]);
            eepA = pk2(ee, ee);
        }
        {
            float ssq = 0.f;
            #pragma unroll
            for (int c = 0; c < 8; c++) ssq = __fadd_rn(ssq, __fmul_rn(e1[c], e1[c]));
            const float rho = fmaxf(__fsqrt_rn(ssq), 1e-12f);
            float en[8], ee = 0.f;
            #pragma unroll
            for (int c = 0; c < 8; c++) en[c] = __fdiv_rn(e1[c], rho);
            #pragma unroll
            for (int c = 0; c < 8; c++) ee = __fadd_rn(ee, __fmul_rn(en[c], en[c]));
            #pragma unroll
            for (int c = 0; c < 8; c++) enB[c] = pk2(en[c], en[c]);
            eepB = pk2(ee, ee);
        }
        const unsigned long long m2 = pk2(-2.f, -2.f);

        // ---- argmin: per-token 4-chain first-wins, identical to R13 ----
        float aA = 3.4e38f, aB = 3.4e38f, aC = 3.4e38f, aD = 3.4e38f;
        int   jA = 0, jB = 0, jC = 0, jD = 0;
        float bA_ = 3.4e38f, bB_ = 3.4e38f, bC_ = 3.4e38f, bD_ = 3.4e38f;
        int   kA = 0, kB = 0, kC = 0, kD = 0;
        const unsigned long long* cbu = (const unsigned long long*)&smf[SM_CB2];
        const unsigned long long* ccu = (const unsigned long long*)&smf[SM_CC2];
        for (int k2 = 0; k2 < KK/2; k2 += 2) {
            const ulonglong2 ca0 = *(const ulonglong2*)(cbu + k2*8);
            const ulonglong2 cb0 = *(const ulonglong2*)(cbu + k2*8 + 2);
            const ulonglong2 cc0 = *(const ulonglong2*)(cbu + k2*8 + 4);
            const ulonglong2 cd0 = *(const ulonglong2*)(cbu + k2*8 + 6);
            const ulonglong2 ca1 = *(const ulonglong2*)(cbu + (k2+1)*8);
            const ulonglong2 cb1 = *(const ulonglong2*)(cbu + (k2+1)*8 + 2);
            const ulonglong2 cc1 = *(const ulonglong2*)(cbu + (k2+1)*8 + 4);
            const ulonglong2 cd1 = *(const ulonglong2*)(cbu + (k2+1)*8 + 6);
            const unsigned long long ccv0 = ccu[k2], ccv1 = ccu[k2+1];
            {
                unsigned long long dp0 = fmul2(enA[0], ca0.x);
                unsigned long long dp1 = fmul2(enA[0], ca1.x);
                dp0 = ffma2(enA[1], ca0.y, dp0);  dp1 = ffma2(enA[1], ca1.y, dp1);
                dp0 = ffma2(enA[2], cb0.x, dp0);  dp1 = ffma2(enA[2], cb1.x, dp1);
                dp0 = ffma2(enA[3], cb0.y, dp0);  dp1 = ffma2(enA[3], cb1.y, dp1);
                dp0 = ffma2(enA[4], cc0.x, dp0);  dp1 = ffma2(enA[4], cc1.x, dp1);
                dp0 = ffma2(enA[5], cc0.y, dp0);  dp1 = ffma2(enA[5], cc1.y, dp1);
                dp0 = ffma2(enA[6], cd0.x, dp0);  dp1 = ffma2(enA[6], cd1.x, dp1);
                dp0 = ffma2(enA[7], cd0.y, dp0);  dp1 = ffma2(enA[7], cd1.y, dp1);
                const unsigned long long t0 = ffma2(m2, dp0, eepA);
                const unsigned long long t1 = ffma2(m2, dp1, eepA);
                const unsigned long long di0 = fadd2(t0, ccv0);
                const unsigned long long di1 = fadd2(t1, ccv1);
                float d0v, d1v, d2v, d3v;
                upk2(di0, d0v, d1v); upk2(di1, d2v, d3v);
                if (d0v < aA) { aA = d0v; jA = 2*k2; }
                if (d1v < aB) { aB = d1v; jB = 2*k2 + 1; }
                if (d2v < aC) { aC = d2v; jC = 2*k2 + 2; }
                if (d3v < aD) { aD = d3v; jD = 2*k2 + 3; }
            }
            {
                unsigned long long dp0 = fmul2(enB[0], ca0.x);
                unsigned long long dp1 = fmul2(enB[0], ca1.x);
                dp0 = ffma2(enB[1], ca0.y, dp0);  dp1 = ffma2(enB[1], ca1.y, dp1);
                dp0 = ffma2(enB[2], cb0.x, dp0);  dp1 = ffma2(enB[2], cb1.x, dp1);
                dp0 = ffma2(enB[3], cb0.y, dp0);  dp1 = ffma2(enB[3], cb1.y, dp1);
                dp0 = ffma2(enB[4], cc0.x, dp0);  dp1 = ffma2(enB[4], cc1.x, dp1);
                dp0 = ffma2(enB[5], cc0.y, dp0);  dp1 = ffma2(enB[5], cc1.y, dp1);
                dp0 = ffma2(enB[6], cd0.x, dp0);  dp1 = ffma2(enB[6], cd1.x, dp1);
                dp0 = ffma2(enB[7], cd0.y, dp0);  dp1 = ffma2(enB[7], cd1.y, dp1);
                const unsigned long long t0 = ffma2(m2, dp0, eepB);
                const unsigned long long t1 = ffma2(m2, dp1, eepB);
                const unsigned long long di0 = fadd2(t0, ccv0);
                const unsigned long long di1 = fadd2(t1, ccv1);
                float d0v, d1v, d2v, d3v;
                upk2(di0, d0v, d1v); upk2(di1, d2v, d3v);
                if (d0v < bA_) { bA_ = d0v; kA = 2*k2; }
                if (d1v < bB_) { bB_ = d1v; kB = 2*k2 + 1; }
                if (d2v < bC_) { bC_ = d2v; kC = 2*k2 + 2; }
                if (d3v < bD_) { bD_ = d3v; kD = 2*k2 + 3; }
            }
        }
        float best0 = aA; int bi0 = jA;
        if (aB < best0 || (aB == best0 && jB < bi0)) { best0 = aB; bi0 = jB; }
        if (aC < best0 || (aC == best0 && jC < bi0)) { best0 = aC; bi0 = jC; }
        if (aD < best0 || (aD == best0 && jD < bi0)) { best0 = aD; bi0 = jD; }
        float best1 = bA_; int bi1 = kA;
        if (bB_ < best1 || (bB_ == best1 && kB < bi1)) { best1 = bB_; bi1 = kB; }
        if (bC_ < best1 || (bC_ == best1 && kC < bi1)) { best1 = bC_; bi1 = kC; }
        if (bD_ < best1 || (bD_ == best1 && kD < bi1)) { best1 = bD_; bi1 = kD; }

        // ---- Phase 3: winners, straight-through, outputs ----
        const float* q0p = cb_raw + ((size_t)n*KK + bi0)*8;
        const float* q1p = cb_raw + ((size_t)n*KK + bi1)*8;
        const float4 qa0 = __ldg((const float4*)q0p);
        const float4 qa1 = __ldg((const float4*)(q0p + 4));
        const float4 qb0 = __ldg((const float4*)q1p);
        const float4 qb1 = __ldg((const float4*)(q1p + 4));
        const float q0[8] = {qa0.x, qa0.y, qa0.z, qa0.w, qa1.x, qa1.y, qa1.z, qa1.w};
        const float q1[8] = {qb0.x, qb0.y, qb0.z, qb0.w, qb1.x, qb1.y, qb1.z, qb1.w};

        #pragma unroll
        for (int c = 0; c < 8; c++) {
            const float dl0 = __fsub_rn(e0[c], q0[c]);
            lacc = fmaf(dl0, dl0, lacc);
            const float dl1 = __fsub_rn(e1[c], q1[c]);
            lacc = fmaf(dl1, dl1, lacc);
            zqA0[c] = __fadd_rn(e0[c], __fsub_rn(q0[c], e0[c]));
            zqA1[c] = __fadd_rn(e1[c], __fsub_rn(q1[c], e1[c]));
        }

        *(float2*)&out[OFF_CODES + (size_t)b*NCB*TT + (size_t)n*TT + t] =
            make_float2((float)bi0, (float)bi1);
        #pragma unroll
        for (int c = 0; c < 8; c++)
            *(float2*)&out[OFF_LAT + (size_t)b*CN*TT + (size_t)(n*8 + c)*TT + t] =
                make_float2(e0[c], e1[c]);
    }

    // ---- Final pass: res7(A) -> proj7 (zq7 from smem) -> proj8 (zqA) -> out ----
    __syncthreads();
    for (int i = tid; i < DD*8; i += THREADS) {
        smf[SM_FW7 + i] = g_WoutT[(size_t)7*DD*8 + i];
        smf[SM_FW8 + i] = g_WoutT[(size_t)8*DD*8 + i];
    }
    for (int i = tid; i < DD; i += THREADS) {
        smf[SM_FO7 + i] = out_b[7*DD + i];
        smf[SM_FO8 + i] = out_b[8*DD + i];
    }
    __syncthreads();

    {
        unsigned long long zb2[8], za2[8];
        #pragma unroll
        for (int c = 0; c < 8; c++) {
            zb2[c] = pk2(zq7s[tid*16 + c], zq7s[tid*16 + 8 + c]);   // zq7
            za2[c] = pk2(zqA0[c], zqA1[c]);                          // zq8
        }
        unsigned long long rb[8], zb[8];
        #pragma unroll
        for (int i = 0; i < 8; i++) {
            rb[i] = *(const unsigned long long*)((const float*)g_resA + off + (size_t)i*TT);
            zb[i] = *(const unsigned long long*)(z + off + (size_t)i*TT);
        }
        for (int d0 = 0; d0 < DD; d0 += 8) {
            unsigned long long rn_[8], zn_[8];
            const bool more = (d0 + 8) < DD;
            if (more) {
                #pragma unroll
                for (int i = 0; i < 8; i++) {
                    rn_[i] = *(const unsigned long long*)((const float*)g_resA + off + (size_t)(d0 + 8 + i)*TT);
                    zn_[i] = *(const unsigned long long*)(z + off + (size_t)(d0 + 8 + i)*TT);
                }
            }
            #pragma unroll
            for (int i = 0; i < 8; i++) {
                const int d = d0 + i;
                unsigned long long r2 = rb[i];
                {   // proj7 with zq7 (exactly what stage 8 computed on the fly)
                    const float4 wa = *(const float4*)&smf[SM_FW7 + d*8];
                    const float4 wb = *(const float4*)&smf[SM_FW7 + d*8 + 4];
                    unsigned long long dt = ffma2(pk2(wa.x, wa.x), zb2[0], 0ull);
                    dt = ffma2(pk2(wa.y, wa.y), zb2[1], dt);
                    dt = ffma2(pk2(wa.z, wa.z), zb2[2], dt);
                    dt = ffma2(pk2(wa.w, wa.w), zb2[3], dt);
                    dt = ffma2(pk2(wb.x, wb.x), zb2[4], dt);
                    dt = ffma2(pk2(wb.y, wb.y), zb2[5], dt);
                    dt = ffma2(pk2(wb.z, wb.z), zb2[6], dt);
                    dt = ffma2(pk2(wb.w, wb.w), zb2[7], dt);
                    const float obv = smf[SM_FO7 + d];
                    const unsigned long long pr = fadd2(dt, pk2(obv, obv));
                    r2 = fadd2(r2, pr ^ SGN2);
                }
                {   // proj8 with zq8
                    const float4 wa = *(const float4*)&smf[SM_FW8 + d*8];
                    const float4 wb = *(const float4*)&smf[SM_FW8 + d*8 + 4];
                    unsigned long long dt = ffma2(pk2(wa.x, wa.x), za2[0], 0ull);
                    dt = ffma2(pk2(wa.y, wa.y), za2[1], dt);
                    dt = ffma2(pk2(wa.z, wa.z), za2[2], dt);
                    dt = ffma2(pk2(wa.w, wa.w), za2[3], dt);
                    dt = ffma2(pk2(wb.x, wb.x), za2[4], dt);
                    dt = ffma2(pk2(wb.y, wb.y), za2[5], dt);
                    dt = ffma2(pk2(wb.z, wb.z), za2[6], dt);
                    dt = ffma2(pk2(wb.w, wb.w), za2[7], dt);
                    const float obv = smf[SM_FO8 + d];
                    const unsigned long long pr = fadd2(dt, pk2(obv, obv));
                    r2 = fadd2(r2, pr ^ SGN2);
                }
                *(unsigned long long*)&out[off + (size_t)d*TT] = fadd2(zb[i], r2 ^ SGN2); // rn(z - r9)
            }
            if (more) {
                #pragma unroll
                for (int i = 0; i < 8; i++) { rb[i] = rn_[i]; zb[i] = zn_[i]; }
            }
        }
    }

    // ---- loss partial ----
    red[tid] = lacc; __syncthreads();
    for (int s = THREADS/2; s > 0; s >>= 1) {
        if (tid < s) red[tid] += red[tid + s];
        __syncthreads();
    }
    if (tid == 0) g_lpart[blockIdx.x] = red[0];
}

// ---------------------------------------------------------------------------
// Deterministic loss reduce in fp64: cl == cbl (identical forward values)
// ---------------------------------------------------------------------------
__global__ void k_loss(float* __restrict__ out) {
    if (threadIdx.x != 0 || blockIdx.x != 0) return;
    double s = 0.0;
    for (int i = 0; i < NBLK; i++) s += (double)g_lpart[i];
    const float v = (float)(s / 524288.0);   // per-stage mean over B*C*T, summed
    out[OFF_CL]     = v;
    out[OFF_CL + 1] = v;
}

// ---------------------------------------------------------------------------
extern "C" void kernel_launch(void* const* d_in, const int* in_sizes, int n_in,
                              void* d_out, int out_size) {
    (void)in_sizes; (void)n_in; (void)out_size;
    const float* z     = (const float*)d_in[0];
    const float* in_v  = (const float*)d_in[1];
    const float* in_g  = (const float*)d_in[2];
    const float* in_b  = (const float*)d_in[3];
    const float* out_v = (const float*)d_in[4];
    const float* out_g = (const float*)d_in[5];
    const float* out_b = (const float*)d_in[6];
    const float* cb    = (const float*)d_in[7];
    float* out = (float*)d_out;

    cudaFuncSetAttribute(k_mega, cudaFuncAttributeMaxDynamicSharedMemorySize, SMEM_TOT);

    kp_win  <<<72, 256>>>(in_v, in_g);
    kp_wout <<<(NCB*DD + 255)/256, 256>>>(out_v, out_g);
    kp_cb   <<<(NCB*KK + 255)/256, 256>>>(cb);

    k_mega <<<NBLK, THREADS, SMEM_TOT>>>(z, in_b, out_b, cb, out);
    k_loss <<<1, 32>>>(out);
}